// round 14
// baseline (speedup 1.0000x reference)
#include <cuda_runtime.h>
#include <cuda_fp16.h>
#include <cstdint>

#define NTOT 8192
#define BB   8
#define NBAT 1024
#define KK   9
#define CC   32
#define CMID 128
#define MM   9216        // NBAT*KK per batch
#define KSPLIT 9
#define KPART  1024      // MM / KSPLIT
#define NCH    32        // KPART / 32
#define HF_GRID 128
#define BSTR   36        // k_main sB row stride in words

typedef unsigned long long u64;

// ---------------- scratch (device globals; no allocation anywhere) ----------
__device__ __half  g_convwT[BB * CC * MM];  // [b][c][m], fp16
__device__ float4  g_abxy[BB * MM];         // (am, bx, by, 0) per m
__device__ float   g_part[KSPLIT * NTOT * CC];
__device__ float   g_sx[CC], g_sx2[CC], g_sh[CMID], g_sh2[CMID];
__device__ int     g_cntx;                  // k_hf barrier 0 counter
__device__ int     g_cnth;                  // k_hf barrier 1 counter

// ---------------- helpers ----------------------------------------------------
__device__ __forceinline__ uint32_t ex2h2(float lo, float hi) {
    uint32_t h2, r;
    asm("cvt.rn.f16x2.f32 %0, %1, %2;" : "=r"(h2) : "f"(hi), "f"(lo));
    asm("ex2.approx.f16x2 %0, %1;" : "=r"(r) : "r"(h2));
    return r;
}
__device__ __forceinline__ uint32_t packh2(float lo, float hi) {
    uint32_t h2;
    asm("cvt.rn.f16x2.f32 %0, %1, %2;" : "=r"(h2) : "f"(hi), "f"(lo));
    return h2;
}
__device__ __forceinline__ u64 pk2(float lo, float hi) {
    u64 r; asm("mov.b64 %0, {%1, %2};" : "=l"(r) : "f"(lo), "f"(hi)); return r;
}
__device__ __forceinline__ u64 fma2(u64 a, u64 b, u64 c) {
    u64 d; asm("fma.rn.f32x2 %0, %1, %2, %3;" : "=l"(d) : "l"(a), "l"(b), "l"(c));
    return d;
}
__device__ __forceinline__ u64 add2(u64 a, u64 b) {
    u64 d; asm("add.rn.f32x2 %0, %1, %2;" : "=l"(d) : "l"(a), "l"(b));
    return d;
}
__device__ __forceinline__ uint32_t ex2h2p(u64 v) {
    float lo, hi;
    asm("mov.b64 {%0, %1}, %2;" : "=f"(lo), "=f"(hi) : "l"(v));
    return ex2h2(lo, hi);
}
__device__ __forceinline__ void mma_f16(float* d,
                                        uint32_t a0, uint32_t a1,
                                        uint32_t a2, uint32_t a3,
                                        uint32_t b0, uint32_t b1) {
    asm volatile(
        "mma.sync.aligned.m16n8k16.row.col.f32.f16.f16.f32 "
        "{%0,%1,%2,%3}, {%4,%5,%6,%7}, {%8,%9}, {%0,%1,%2,%3};"
        : "+f"(d[0]), "+f"(d[1]), "+f"(d[2]), "+f"(d[3])
        : "r"(a0), "r"(a1), "r"(a2), "r"(a3), "r"(b0), "r"(b1));
}

#define LOG2E 1.4426950408889634f
#define C2    (-2.0f * LOG2E)

// ---------------- K1: conv_w via fp16 MMA + abxy + zero counters ------------
// grid 128 (64 n per block), 256 threads (unchanged — verified)
#define PS_SKW  0        // 288*20 = 5760  (B: [j][c-pair], fp16)
#define PS_SW   5760     // 64*20  = 1280  (A: [n][c-pair], fp16)
#define PS_ST   7040     // 64*148 = 9472  (out staging: [n][col-pair], fp16)
#define PS_SP   16512    // 128 floats
#define PS_SKP  16640    // 18 floats
#define PS_WORDS 16660   // 66640 bytes

__global__ void __launch_bounds__(256) k_prep(const float* __restrict__ pos,
                                              const float* __restrict__ wts,
                                              const float* __restrict__ kpos,
                                              const float* __restrict__ kw) {
    extern __shared__ uint32_t ps[];
    uint32_t* skw = ps + PS_SKW;
    uint32_t* sw  = ps + PS_SW;
    uint32_t* st  = ps + PS_ST;
    float*  sp  = (float*)(ps + PS_SP);
    float*  skp = (float*)(ps + PS_SKP);
    __half* skwh = (__half*)skw;
    __half* sth  = (__half*)st;
    int tid = threadIdx.x;
    int n0 = blockIdx.x * 64;          // global n
    int b  = n0 >> 10;
    int m0 = (n0 & 1023) * KK;         // m within batch
    if (blockIdx.x == 0) {             // re-zero per replay
        if (tid < CC)   { g_sx[tid] = 0.f; g_sx2[tid] = 0.f; }
        if (tid < CMID) { g_sh[tid] = 0.f; g_sh2[tid] = 0.f; }
        if (tid == CMID)     g_cntx = 0;
        if (tid == CMID + 1) g_cnth = 0;
    }
    #pragma unroll
    for (int i = 0; i < 4; i++) {
        int wdx = tid + 256 * i;       // 0..1023 (64 rows x 16 pairs)
        int n = wdx >> 4, cp = wdx & 15;
        float2 v = ((const float2*)wts)[(size_t)(n0 + n) * 16 + cp];
        sw[n * 20 + cp] = packh2(v.x, v.y);
    }
    #pragma unroll
    for (int i = 0; i < 36; i++) {
        int flat = tid + 256 * i;      // 0..9215
        int d = flat & 31, c = (flat >> 5) & 31, k = flat >> 10;
        skwh[(k * 32 + d) * 40 + c] = __float2half_rn(kw[flat]);
    }
    if (tid < 128) sp[tid] = pos[n0 * 2 + tid];
    if (tid < KK * 2) skp[tid] = kpos[tid];
    __syncthreads();
    #pragma unroll
    for (int i = 0; i < 3; i++) {
        int idx = tid + 256 * i;
        if (idx < 576) {
            int n = idx / KK, kk2 = idx - KK * (idx / KK);
            float cpx = sp[2 * n]     + skp[2 * kk2];
            float cpy = sp[2 * n + 1] + skp[2 * kk2 + 1];
            float am  = C2 * fmaf(cpx, cpx, cpy * cpy);
            g_abxy[(size_t)b * MM + m0 + idx] =
                make_float4(am, 4.f * LOG2E * cpx, 4.f * LOG2E * cpy, 0.f);
        }
    }
    int w = tid >> 5, lane = tid & 31;
    int g = lane >> 2, t = lane & 3;
    int wr = w & 3, wc = w >> 2;
    int arow0 = (16 * wr + g) * 20;
    int arow1 = (16 * wr + g + 8) * 20;
    float acc[18][4];
    #pragma unroll
    for (int i = 0; i < 18; i++)
        #pragma unroll
        for (int q = 0; q < 4; q++) acc[i][q] = 0.f;
    #pragma unroll
    for (int s = 0; s < 2; s++) {
        uint32_t a0 = sw[arow0 + t + 8 * s];
        uint32_t a1 = sw[arow1 + t + 8 * s];
        uint32_t a2 = sw[arow0 + t + 8 * s + 4];
        uint32_t a3 = sw[arow1 + t + 8 * s + 4];
        #pragma unroll
        for (int i = 0; i < 18; i++) {
            int brow = (wc * 144 + i * 8 + g) * 20;
            uint32_t b0 = skw[brow + 8 * s + t];
            uint32_t b1 = skw[brow + 8 * s + t + 4];
            mma_f16(acc[i], a0, a1, a2, a3, b0, b1);
        }
    }
    #pragma unroll
    for (int i = 0; i < 18; i++) {
        int cpair = wc * 72 + i * 4 + t;
        st[(16 * wr + g) * 148 + cpair]     = packh2(acc[i][0], acc[i][1]);
        st[(16 * wr + g + 8) * 148 + cpair] = packh2(acc[i][2], acc[i][3]);
    }
    __syncthreads();
    #pragma unroll
    for (int i = 0; i < 36; i++) {
        int flat = tid + 256 * i;      // 0..9215 (288 m-pairs x 32 c)
        int c  = flat / 288;
        int mp = flat - c * 288;
        int mm = 2 * mp;
        int n1 = mm / KK, k1 = mm - KK * n1;
        int mmb = mm + 1;
        int n2 = mmb / KK, k2 = mmb - KK * n2;
        __half v0 = sth[n1 * 296 + k1 * 32 + c];
        __half v1 = sth[n2 * 296 + k2 * 32 + c];
        __half2 pv = __halves2half2(v0, v1);
        *(uint32_t*)((__half*)g_convwT + ((size_t)b * CC + c) * MM + m0 + mm) =
            *(uint32_t*)&pv;
    }
}

// ---------------- K2: Kmat @ conv_w via mma.sync fp16 (m16n8k16) ------------
// grid 144; 512 threads = 16 warps, 32x32 tile per warp. A-gen now uses
// f32x2 packed FMA (halves FMA-pipe pressure of the exponent arguments).
__global__ void __launch_bounds__(512) k_main(const float* __restrict__ pos) {
    __shared__ uint32_t sB[2][32 * BSTR];
    __shared__ float4   sAB[2][32];
    int tid  = threadIdx.x;
    int w    = tid >> 5, lane = tid & 31;
    int g    = lane >> 2, t = lane & 3;
    int blk  = blockIdx.x;
    int b   = blk / 18;
    int rem = blk - b * 18;
    int rb  = rem / 9;
    int ks  = rem - rb * 9;
    int ctabase = b * NBAT + rb * 512;
    int rbase   = ctabase + w * 32;
    size_t mbase = (size_t)b * MM + (size_t)ks * KPART;

    int sc = tid >> 3, sq = tid & 7;
    const uint2* gB = (const uint2*)(g_convwT + ((size_t)b * CC + sc) * MM
                                     + (size_t)ks * KPART);
    const float4* gAB = g_abxy + mbase;

    // packed per-lane row data (lo == hi; pairs broadcast across m-pair)
    u64 px2[4], py2[4], pp2[4];
    #pragma unroll
    for (int u = 0; u < 4; u++) {
        float2 p = ((const float2*)pos)[rbase + g + 8 * u];
        float pp = C2 * fmaf(p.x, p.x, p.y * p.y);
        px2[u] = pk2(p.x, p.x);
        py2[u] = pk2(p.y, p.y);
        pp2[u] = pk2(pp, pp);
    }
    float acc[2][4][4];
    #pragma unroll
    for (int j = 0; j < 2; j++)
        #pragma unroll
        for (int i = 0; i < 4; i++)
            #pragma unroll
            for (int q = 0; q < 4; q++) acc[j][i][q] = 0.f;

    if (tid < 256) {
        uint2 v = gB[sq];
        sB[0][sc * BSTR + sq * 2]     = v.x;
        sB[0][sc * BSTR + sq * 2 + 1] = v.y;
    }
    if (tid < 32) sAB[0][tid] = gAB[tid];
    for (int tc = 0; tc < NCH; tc++) {
        int buf = tc & 1;
        __syncthreads();
        if (tc + 1 < NCH) {
            if (tid < 256) {
                uint2 v = gB[(tc + 1) * 8 + sq];
                sB[buf ^ 1][sc * BSTR + sq * 2]     = v.x;
                sB[buf ^ 1][sc * BSTR + sq * 2 + 1] = v.y;
            }
            if (tid < 32) sAB[buf ^ 1][tid] = gAB[(tc + 1) * 32 + tid];
        }
        uint32_t A16[4][4];
        #pragma unroll
        for (int v = 0; v < 4; v++) {
            float4 qa = sAB[buf][2 * t + 8 * v];
            float4 qb = sAB[buf][2 * t + 8 * v + 1];
            u64 am2 = pk2(qa.x, qb.x);
            u64 bx2 = pk2(qa.y, qb.y);
            u64 by2 = pk2(qa.z, qb.z);
            #pragma unroll
            for (int u = 0; u < 4; u++) {
                u64 tt = fma2(bx2, px2[u], am2);
                tt = fma2(by2, py2[u], tt);
                tt = add2(tt, pp2[u]);
                A16[u][v] = ex2h2p(tt);
            }
        }
        #pragma unroll
        for (int i = 0; i < 4; i++) {
            int base = (i * 8 + g) * BSTR;
            #pragma unroll
            for (int s = 0; s < 2; s++) {
                uint32_t b0 = sB[buf][base + 8 * s + t];
                uint32_t b1 = sB[buf][base + 8 * s + t + 4];
                #pragma unroll
                for (int j = 0; j < 2; j++)
                    mma_f16(acc[j][i],
                            A16[2*j][2*s],   A16[2*j+1][2*s],
                            A16[2*j][2*s+1], A16[2*j+1][2*s+1],
                            b0, b1);
            }
        }
    }
    #pragma unroll
    for (int j = 0; j < 2; j++) {
        int nr0 = rbase + j * 16 + g;
        #pragma unroll
        for (int i = 0; i < 4; i++) {
            int c = i * 8 + t * 2;
            *(float2*)&g_part[((size_t)ks * NTOT + nr0) * CC + c] =
                make_float2(acc[j][i][0], acc[j][i][1]);
            *(float2*)&g_part[((size_t)ks * NTOT + nr0 + 8) * CC + c] =
                make_float2(acc[j][i][2], acc[j][i][3]);
        }
    }
}

// ---------------- K3: reduce -> x-stats -> xn -> h -> BN(h) -> W2 -> out ----
#define HF_SXN  0        // 64*32   = 2048
#define HF_SW1  2048     // 32*128  = 4096
#define HF_SH   6144     // 64*128  = 8192
#define HF_SW2  14336    // 128*34  = 4352
#define HF_SB2  18688    // 48
#define HF_SXS  18736    // 32
#define HF_SXH  18768    // 32
#define HF_SHS  18800    // 128
#define HF_SHH  18928    // 128
#define HF_RED  19056    // 512
#define HF_FLOATS 19568  // 78272 bytes

__global__ void __launch_bounds__(512) k_hf(const float* __restrict__ pos,
                                            const float* __restrict__ wts,
                                            const float* __restrict__ W1,
                                            const float* __restrict__ b1,
                                            const float* __restrict__ cng,
                                            const float* __restrict__ cnb,
                                            const float* __restrict__ bng,
                                            const float* __restrict__ bnb,
                                            const float* __restrict__ W2,
                                            const float* __restrict__ b2,
                                            float* __restrict__ out) {
    extern __shared__ float dyn[];
    float* sxn = dyn + HF_SXN;
    float* sW1 = dyn + HF_SW1;
    float* sh  = dyn + HF_SH;
    float* sW2 = dyn + HF_SW2;
    float* sb2 = dyn + HF_SB2;
    float* sxs = dyn + HF_SXS;
    float* sxh = dyn + HF_SXH;
    float* shs = dyn + HF_SHS;
    float* shh = dyn + HF_SHH;
    float* red = dyn + HF_RED;
    int tid = threadIdx.x;
    int n0 = blockIdx.x * 64;
    #pragma unroll
    for (int i = 0; i < 8; i++) sW1[tid + 512 * i] = W1[tid + 512 * i];
    for (int i = tid; i < CMID * 34; i += 512) sW2[i] = W2[i];
    if (tid < 34) sb2[tid] = b2[tid];
    {
        int n = tid >> 3, c4 = (tid & 7) * 4;
        const float4* base = (const float4*)(g_part
                              + (size_t)(n0 + n) * CC + c4);
        float4 a = base[0];
        #pragma unroll
        for (int s = 1; s < KSPLIT; s++) {
            float4 v = base[(size_t)s * (NTOT * CC / 4)];
            a.x += v.x; a.y += v.y; a.z += v.z; a.w += v.w;
        }
        a.x = a.x >= 0.f ? a.x : 0.01f * a.x;
        a.y = a.y >= 0.f ? a.y : 0.01f * a.y;
        a.z = a.z >= 0.f ? a.z : 0.01f * a.z;
        a.w = a.w >= 0.f ? a.w : 0.01f * a.w;
        *(float4*)&sxn[n * CC + c4] = a;
    }
    __syncthreads();
    {
        int c = tid & 31, rs = tid >> 5;
        float sx = 0.f, sx2 = 0.f;
        #pragma unroll
        for (int i = 0; i < 4; i++) {
            float v = sxn[(rs + 16 * i) * CC + c];
            sx += v; sx2 += v * v;
        }
        red[tid] = sx; __syncthreads();
        if (rs == 0) {
            float s = 0.f;
            #pragma unroll
            for (int j = 0; j < 16; j++) s += red[c + 32 * j];
            atomicAdd(&g_sx[c], s);
        }
        __syncthreads(); red[tid] = sx2; __syncthreads();
        if (rs == 0) {
            float s = 0.f;
            #pragma unroll
            for (int j = 0; j < 16; j++) s += red[c + 32 * j];
            atomicAdd(&g_sx2[c], s);
        }
    }
    __threadfence();
    __syncthreads();
    if (tid == 0) {
        atomicAdd(&g_cntx, 1);
        while (*(volatile int*)&g_cntx < HF_GRID) { }
    }
    __syncthreads();
    __threadfence();
    if (tid < CC) {
        float mu  = g_sx[tid] * (1.f / NTOT);
        float var = fmaf(-mu, mu, g_sx2[tid] * (1.f / NTOT));
        float rsv = rsqrtf(var + 1e-5f);
        float gs  = cng[tid] * rsv;
        sxs[tid] = gs;
        sxh[tid] = fmaf(-gs, mu, cnb[tid]);
    }
    __syncthreads();
    #pragma unroll
    for (int i = 0; i < 4; i++) {
        int idx = tid + 512 * i;
        int rr = idx >> 5, c = idx & 31;
        sxn[idx] = fmaf(sxs[c], sxn[idx], sxh[c])
                   + wts[(size_t)(n0 + rr) * CC + c];
    }
    __syncthreads();
    int c = tid & 127, rg = tid >> 7;
    float wreg[CC];
    #pragma unroll
    for (int cin = 0; cin < CC; cin++) wreg[cin] = sW1[cin * CMID + c];
    float bc = b1[c];
    float shsum = 0.f, sh2sum = 0.f;
    for (int i = 0; i < 16; i++) {
        int rr = rg + 4 * i;
        const float4* xr4 = (const float4*)&sxn[rr * CC];
        float a0 = bc, a1 = 0.f;
        #pragma unroll
        for (int q = 0; q < 4; q++) {
            float4 v0 = xr4[q], v1 = xr4[q + 4];
            a0 = fmaf(v0.x, wreg[4*q+0],  a0);
            a1 = fmaf(v1.x, wreg[16+4*q+0], a1);
            a0 = fmaf(v0.y, wreg[4*q+1],  a0);
            a1 = fmaf(v1.y, wreg[16+4*q+1], a1);
            a0 = fmaf(v0.z, wreg[4*q+2],  a0);
            a1 = fmaf(v1.z, wreg[16+4*q+2], a1);
            a0 = fmaf(v0.w, wreg[4*q+3],  a0);
            a1 = fmaf(v1.w, wreg[16+4*q+3], a1);
        }
        float a = a0 + a1;
        float hh = a >= 0.f ? a : 0.01f * a;
        sh[rr * CMID + c] = hh;
        shsum += hh; sh2sum += hh * hh;
    }
    red[tid] = shsum; __syncthreads();
    if (rg == 0) atomicAdd(&g_sh[c], red[c] + red[c + 128] + red[c + 256] + red[c + 384]);
    __syncthreads(); red[tid] = sh2sum; __syncthreads();
    if (rg == 0) atomicAdd(&g_sh2[c], red[c] + red[c + 128] + red[c + 256] + red[c + 384]);
    __threadfence();
    __syncthreads();
    if (tid == 0) {
        atomicAdd(&g_cnth, 1);
        while (*(volatile int*)&g_cnth < HF_GRID) { }
    }
    __syncthreads();
    __threadfence();
    if (tid < CMID) {
        float mu  = g_sh[tid] * (1.f / NTOT);
        float var = fmaf(-mu, mu, g_sh2[tid] * (1.f / NTOT));
        float rsv = rsqrtf(var + 1e-5f);
        float gs  = bng[tid] * rsv;
        shs[tid] = gs;
        shh[tid] = fmaf(-gs, mu, bnb[tid]);
    }
    __syncthreads();
    #pragma unroll
    for (int i = 0; i < 16; i++) {
        int idx = tid + 512 * i;
        int cc = idx & 127;
        sh[idx] = fmaf(shs[cc], sh[idx], shh[cc]);
    }
    __syncthreads();
    int w = tid >> 5, lane = tid & 31;
    float* out_pos = out;
    float* out_w   = out + NTOT * 2;
    #pragma unroll
    for (int r = 0; r < 4; r++) {
        int lr = w * 4 + r;
        int n  = n0 + lr;
        const float* hr = &sh[lr * CMID];
        float acc1 = sb2[lane];
        #pragma unroll 8
        for (int cin = 0; cin < CMID; cin++)
            acc1 = fmaf(hr[cin], sW2[cin * 34 + lane], acc1);
        if (lane < 2) {
            out_pos[n * 2 + lane] = pos[n * 2 + lane] + acc1;
            float acc2 = sb2[32 + lane];
            #pragma unroll 8
            for (int cin = 0; cin < CMID; cin++)
                acc2 = fmaf(hr[cin], sW2[cin * 34 + 32 + lane], acc2);
            out_w[n * CC + 30 + lane] = sxn[lr * CC + 30 + lane] + acc2;
        } else {
            out_w[n * CC + lane - 2] = sxn[lr * CC + lane - 2] + acc1;
        }
    }
}

// ---------------- launch ----------------------------------------------------
extern "C" void kernel_launch(void* const* d_in, const int* in_sizes, int n_in,
                              void* d_out, int out_size) {
    const float* positions = (const float*)d_in[0];
    const float* weights   = (const float*)d_in[1];
    const float* kpos = (const float*)d_in[3];
    const float* kw   = (const float*)d_in[4];
    const float* cng  = (const float*)d_in[5];
    const float* cnb  = (const float*)d_in[6];
    const float* W1   = (const float*)d_in[7];
    const float* b1   = (const float*)d_in[8];
    const float* bng  = (const float*)d_in[9];
    const float* bnb  = (const float*)d_in[10];
    const float* W2   = (const float*)d_in[11];
    const float* b2   = (const float*)d_in[12];
    float* out = (float*)d_out;

    cudaFuncSetAttribute(k_prep, cudaFuncAttributeMaxDynamicSharedMemorySize,
                         PS_WORDS * 4);
    cudaFuncSetAttribute(k_hf, cudaFuncAttributeMaxDynamicSharedMemorySize,
                         HF_FLOATS * 4);
    k_prep<<<128, 256, PS_WORDS * 4>>>(positions, weights, kpos, kw);
    k_main<<<144, 512>>>(positions);
    k_hf<<<HF_GRID, 512, HF_FLOATS * 4>>>(positions, weights, W1, b1,
                                          cng, cnb, bng, bnb, W2, b2, out);
}

// round 15
// speedup vs baseline: 1.0684x; 1.0684x over previous
#include <cuda_runtime.h>
#include <cuda_fp16.h>
#include <cstdint>

#define NTOT 8192
#define BB   8
#define NBAT 1024
#define KK   9
#define CC   32
#define CMID 128
#define MM   9216        // NBAT*KK per batch
#define KSPLIT 9
#define KPART  1024      // MM / KSPLIT
#define NCH    32        // KPART / 32
#define HF_GRID 128
#define BSTR   36        // k_main sB row stride in words

// ---------------- scratch (device globals; no allocation anywhere) ----------
__device__ __half  g_convwT[BB * CC * MM];  // [b][c][m], fp16
__device__ float4  g_abxy[BB * MM];         // (am, bx, by, 0) per m
__device__ __half  g_parth[KSPLIT * NTOT * CC];   // fp16 partials
__device__ float   g_sx[CC], g_sx2[CC], g_sh[CMID], g_sh2[CMID];
__device__ int     g_cntx;                  // k_hf barrier 0 counter
__device__ int     g_cnth;                  // k_hf barrier 1 counter

// ---------------- helpers ----------------------------------------------------
__device__ __forceinline__ uint32_t ex2h2(float lo, float hi) {
    uint32_t h2, r;
    asm("cvt.rn.f16x2.f32 %0, %1, %2;" : "=r"(h2) : "f"(hi), "f"(lo));
    asm("ex2.approx.f16x2 %0, %1;" : "=r"(r) : "r"(h2));
    return r;
}
__device__ __forceinline__ uint32_t packh2(float lo, float hi) {
    uint32_t h2;
    asm("cvt.rn.f16x2.f32 %0, %1, %2;" : "=r"(h2) : "f"(hi), "f"(lo));
    return h2;
}
__device__ __forceinline__ void mma_f16(float* d,
                                        uint32_t a0, uint32_t a1,
                                        uint32_t a2, uint32_t a3,
                                        uint32_t b0, uint32_t b1) {
    asm volatile(
        "mma.sync.aligned.m16n8k16.row.col.f32.f16.f16.f32 "
        "{%0,%1,%2,%3}, {%4,%5,%6,%7}, {%8,%9}, {%0,%1,%2,%3};"
        : "+f"(d[0]), "+f"(d[1]), "+f"(d[2]), "+f"(d[3])
        : "r"(a0), "r"(a1), "r"(a2), "r"(a3), "r"(b0), "r"(b1));
}

#define LOG2E 1.4426950408889634f
#define C2    (-2.0f * LOG2E)

// ---------------- K1: conv_w via fp16 MMA + abxy + zero counters ------------
// grid 128 (64 n per block), 256 threads (unchanged — verified)
#define PS_SKW  0        // 288*20 = 5760  (B: [j][c-pair], fp16)
#define PS_SW   5760     // 64*20  = 1280  (A: [n][c-pair], fp16)
#define PS_ST   7040     // 64*148 = 9472  (out staging: [n][col-pair], fp16)
#define PS_SP   16512    // 128 floats
#define PS_SKP  16640    // 18 floats
#define PS_WORDS 16660   // 66640 bytes

__global__ void __launch_bounds__(256) k_prep(const float* __restrict__ pos,
                                              const float* __restrict__ wts,
                                              const float* __restrict__ kpos,
                                              const float* __restrict__ kw) {
    extern __shared__ uint32_t ps[];
    uint32_t* skw = ps + PS_SKW;
    uint32_t* sw  = ps + PS_SW;
    uint32_t* st  = ps + PS_ST;
    float*  sp  = (float*)(ps + PS_SP);
    float*  skp = (float*)(ps + PS_SKP);
    __half* skwh = (__half*)skw;
    __half* sth  = (__half*)st;
    int tid = threadIdx.x;
    int n0 = blockIdx.x * 64;          // global n
    int b  = n0 >> 10;
    int m0 = (n0 & 1023) * KK;         // m within batch
    if (blockIdx.x == 0) {             // re-zero per replay
        if (tid < CC)   { g_sx[tid] = 0.f; g_sx2[tid] = 0.f; }
        if (tid < CMID) { g_sh[tid] = 0.f; g_sh2[tid] = 0.f; }
        if (tid == CMID)     g_cntx = 0;
        if (tid == CMID + 1) g_cnth = 0;
    }
    #pragma unroll
    for (int i = 0; i < 4; i++) {
        int wdx = tid + 256 * i;       // 0..1023 (64 rows x 16 pairs)
        int n = wdx >> 4, cp = wdx & 15;
        float2 v = ((const float2*)wts)[(size_t)(n0 + n) * 16 + cp];
        sw[n * 20 + cp] = packh2(v.x, v.y);
    }
    #pragma unroll
    for (int i = 0; i < 36; i++) {
        int flat = tid + 256 * i;      // 0..9215
        int d = flat & 31, c = (flat >> 5) & 31, k = flat >> 10;
        skwh[(k * 32 + d) * 40 + c] = __float2half_rn(kw[flat]);
    }
    if (tid < 128) sp[tid] = pos[n0 * 2 + tid];
    if (tid < KK * 2) skp[tid] = kpos[tid];
    __syncthreads();
    #pragma unroll
    for (int i = 0; i < 3; i++) {
        int idx = tid + 256 * i;
        if (idx < 576) {
            int n = idx / KK, kk2 = idx - KK * (idx / KK);
            float cpx = sp[2 * n]     + skp[2 * kk2];
            float cpy = sp[2 * n + 1] + skp[2 * kk2 + 1];
            float am  = C2 * fmaf(cpx, cpx, cpy * cpy);
            g_abxy[(size_t)b * MM + m0 + idx] =
                make_float4(am, 4.f * LOG2E * cpx, 4.f * LOG2E * cpy, 0.f);
        }
    }
    int w = tid >> 5, lane = tid & 31;
    int g = lane >> 2, t = lane & 3;
    int wr = w & 3, wc = w >> 2;
    int arow0 = (16 * wr + g) * 20;
    int arow1 = (16 * wr + g + 8) * 20;
    float acc[18][4];
    #pragma unroll
    for (int i = 0; i < 18; i++)
        #pragma unroll
        for (int q = 0; q < 4; q++) acc[i][q] = 0.f;
    #pragma unroll
    for (int s = 0; s < 2; s++) {
        uint32_t a0 = sw[arow0 + t + 8 * s];
        uint32_t a1 = sw[arow1 + t + 8 * s];
        uint32_t a2 = sw[arow0 + t + 8 * s + 4];
        uint32_t a3 = sw[arow1 + t + 8 * s + 4];
        #pragma unroll
        for (int i = 0; i < 18; i++) {
            int brow = (wc * 144 + i * 8 + g) * 20;
            uint32_t b0 = skw[brow + 8 * s + t];
            uint32_t b1 = skw[brow + 8 * s + t + 4];
            mma_f16(acc[i], a0, a1, a2, a3, b0, b1);
        }
    }
    #pragma unroll
    for (int i = 0; i < 18; i++) {
        int cpair = wc * 72 + i * 4 + t;
        st[(16 * wr + g) * 148 + cpair]     = packh2(acc[i][0], acc[i][1]);
        st[(16 * wr + g + 8) * 148 + cpair] = packh2(acc[i][2], acc[i][3]);
    }
    __syncthreads();
    #pragma unroll
    for (int i = 0; i < 36; i++) {
        int flat = tid + 256 * i;      // 0..9215 (288 m-pairs x 32 c)
        int c  = flat / 288;
        int mp = flat - c * 288;
        int mm = 2 * mp;
        int n1 = mm / KK, k1 = mm - KK * n1;
        int mmb = mm + 1;
        int n2 = mmb / KK, k2 = mmb - KK * n2;
        __half v0 = sth[n1 * 296 + k1 * 32 + c];
        __half v1 = sth[n2 * 296 + k2 * 32 + c];
        __half2 pv = __halves2half2(v0, v1);
        *(uint32_t*)((__half*)g_convwT + ((size_t)b * CC + c) * MM + m0 + mm) =
            *(uint32_t*)&pv;
    }
}

// ---------------- K2: Kmat @ conv_w via mma.sync fp16 (m16n8k16) ------------
// grid 144; 512 threads = 16 warps, 32x32 tile per warp.
// A-gen: scalar fp32 (Round-13 form — the f32x2 packed variant regressed).
// Partials stored as fp16 (halves store+reload traffic).
__global__ void __launch_bounds__(512) k_main(const float* __restrict__ pos) {
    __shared__ uint32_t sB[2][32 * BSTR];
    __shared__ float4   sAB[2][32];
    int tid  = threadIdx.x;
    int w    = tid >> 5, lane = tid & 31;
    int g    = lane >> 2, t = lane & 3;
    int blk  = blockIdx.x;
    int b   = blk / 18;
    int rem = blk - b * 18;
    int rb  = rem / 9;
    int ks  = rem - rb * 9;
    int ctabase = b * NBAT + rb * 512;
    int rbase   = ctabase + w * 32;
    size_t mbase = (size_t)b * MM + (size_t)ks * KPART;

    int sc = tid >> 3, sq = tid & 7;
    const uint2* gB = (const uint2*)(g_convwT + ((size_t)b * CC + sc) * MM
                                     + (size_t)ks * KPART);
    const float4* gAB = g_abxy + mbase;

    float px[4], py[4], pp[4];
    #pragma unroll
    for (int u = 0; u < 4; u++) {
        float2 p = ((const float2*)pos)[rbase + g + 8 * u];
        px[u] = p.x; py[u] = p.y;
        pp[u] = C2 * fmaf(p.x, p.x, p.y * p.y);
    }
    float acc[2][4][4];
    #pragma unroll
    for (int j = 0; j < 2; j++)
        #pragma unroll
        for (int i = 0; i < 4; i++)
            #pragma unroll
            for (int q = 0; q < 4; q++) acc[j][i][q] = 0.f;

    if (tid < 256) {
        uint2 v = gB[sq];
        sB[0][sc * BSTR + sq * 2]     = v.x;
        sB[0][sc * BSTR + sq * 2 + 1] = v.y;
    }
    if (tid < 32) sAB[0][tid] = gAB[tid];
    for (int tc = 0; tc < NCH; tc++) {
        int buf = tc & 1;
        __syncthreads();
        if (tc + 1 < NCH) {
            if (tid < 256) {
                uint2 v = gB[(tc + 1) * 8 + sq];
                sB[buf ^ 1][sc * BSTR + sq * 2]     = v.x;
                sB[buf ^ 1][sc * BSTR + sq * 2 + 1] = v.y;
            }
            if (tid < 32) sAB[buf ^ 1][tid] = gAB[(tc + 1) * 32 + tid];
        }
        uint32_t A16[4][4];
        #pragma unroll
        for (int v = 0; v < 4; v++) {
            float4 qa = sAB[buf][2 * t + 8 * v];
            float4 qb = sAB[buf][2 * t + 8 * v + 1];
            #pragma unroll
            for (int u = 0; u < 4; u++) {
                float lo = fmaf(qa.y, px[u], fmaf(qa.z, py[u], pp[u] + qa.x));
                float hi = fmaf(qb.y, px[u], fmaf(qb.z, py[u], pp[u] + qb.x));
                A16[u][v] = ex2h2(lo, hi);
            }
        }
        #pragma unroll
        for (int i = 0; i < 4; i++) {
            int base = (i * 8 + g) * BSTR;
            #pragma unroll
            for (int s = 0; s < 2; s++) {
                uint32_t b0 = sB[buf][base + 8 * s + t];
                uint32_t b1 = sB[buf][base + 8 * s + t + 4];
                #pragma unroll
                for (int j = 0; j < 2; j++)
                    mma_f16(acc[j][i],
                            A16[2*j][2*s],   A16[2*j+1][2*s],
                            A16[2*j][2*s+1], A16[2*j+1][2*s+1],
                            b0, b1);
            }
        }
    }
    // store partials as fp16 pairs
    #pragma unroll
    for (int j = 0; j < 2; j++) {
        int nr0 = rbase + j * 16 + g;
        #pragma unroll
        for (int i = 0; i < 4; i++) {
            int c = i * 8 + t * 2;
            *(uint32_t*)&g_parth[((size_t)ks * NTOT + nr0) * CC + c] =
                packh2(acc[j][i][0], acc[j][i][1]);
            *(uint32_t*)&g_parth[((size_t)ks * NTOT + nr0 + 8) * CC + c] =
                packh2(acc[j][i][2], acc[j][i][3]);
        }
    }
}

// ---------------- K3: reduce -> x-stats -> xn -> h -> BN(h) -> W2 -> out ----
// grid 128, 512 threads; 64 rows/block; TWO grid-wide spin barriers.
#define HF_SXN  0        // 64*32   = 2048
#define HF_SW1  2048     // 32*128  = 4096
#define HF_SH   6144     // 64*128  = 8192
#define HF_SW2  14336    // 128*34  = 4352
#define HF_SB2  18688    // 48
#define HF_SXS  18736    // 32
#define HF_SXH  18768    // 32
#define HF_SHS  18800    // 128
#define HF_SHH  18928    // 128
#define HF_RED  19056    // 512
#define HF_FLOATS 19568  // 78272 bytes

__global__ void __launch_bounds__(512) k_hf(const float* __restrict__ pos,
                                            const float* __restrict__ wts,
                                            const float* __restrict__ W1,
                                            const float* __restrict__ b1,
                                            const float* __restrict__ cng,
                                            const float* __restrict__ cnb,
                                            const float* __restrict__ bng,
                                            const float* __restrict__ bnb,
                                            const float* __restrict__ W2,
                                            const float* __restrict__ b2,
                                            float* __restrict__ out) {
    extern __shared__ float dyn[];
    float* sxn = dyn + HF_SXN;
    float* sW1 = dyn + HF_SW1;
    float* sh  = dyn + HF_SH;
    float* sW2 = dyn + HF_SW2;
    float* sb2 = dyn + HF_SB2;
    float* sxs = dyn + HF_SXS;
    float* sxh = dyn + HF_SXH;
    float* shs = dyn + HF_SHS;
    float* shh = dyn + HF_SHH;
    float* red = dyn + HF_RED;
    int tid = threadIdx.x;
    int n0 = blockIdx.x * 64;
    #pragma unroll
    for (int i = 0; i < 8; i++) sW1[tid + 512 * i] = W1[tid + 512 * i];
    for (int i = tid; i < CMID * 34; i += 512) sW2[i] = W2[i];
    if (tid < 34) sb2[tid] = b2[tid];
    // ---- phase 0: reduce KSPLIT fp16 partials, leaky, local x into smem ----
    {
        int n = tid >> 3, c4 = (tid & 7) * 4;
        const __half2* base = (const __half2*)(g_parth
                              + (size_t)(n0 + n) * CC + c4);
        float2 a01 = __half22float2(base[0]);
        float2 a23 = __half22float2(base[1]);
        #pragma unroll
        for (int s = 1; s < KSPLIT; s++) {
            size_t off = (size_t)s * (NTOT * CC / 2);
            float2 v01 = __half22float2(base[off]);
            float2 v23 = __half22float2(base[off + 1]);
            a01.x += v01.x; a01.y += v01.y;
            a23.x += v23.x; a23.y += v23.y;
        }
        float4 a = make_float4(a01.x, a01.y, a23.x, a23.y);
        a.x = a.x >= 0.f ? a.x : 0.01f * a.x;
        a.y = a.y >= 0.f ? a.y : 0.01f * a.y;
        a.z = a.z >= 0.f ? a.z : 0.01f * a.z;
        a.w = a.w >= 0.f ? a.w : 0.01f * a.w;
        *(float4*)&sxn[n * CC + c4] = a;
    }
    __syncthreads();
    {
        int c = tid & 31, rs = tid >> 5;
        float sx = 0.f, sx2 = 0.f;
        #pragma unroll
        for (int i = 0; i < 4; i++) {
            float v = sxn[(rs + 16 * i) * CC + c];
            sx += v; sx2 += v * v;
        }
        red[tid] = sx; __syncthreads();
        if (rs == 0) {
            float s = 0.f;
            #pragma unroll
            for (int j = 0; j < 16; j++) s += red[c + 32 * j];
            atomicAdd(&g_sx[c], s);
        }
        __syncthreads(); red[tid] = sx2; __syncthreads();
        if (rs == 0) {
            float s = 0.f;
            #pragma unroll
            for (int j = 0; j < 16; j++) s += red[c + 32 * j];
            atomicAdd(&g_sx2[c], s);
        }
    }
    __threadfence();
    __syncthreads();
    if (tid == 0) {
        atomicAdd(&g_cntx, 1);
        while (*(volatile int*)&g_cntx < HF_GRID) { }
    }
    __syncthreads();
    __threadfence();
    if (tid < CC) {
        float mu  = g_sx[tid] * (1.f / NTOT);
        float var = fmaf(-mu, mu, g_sx2[tid] * (1.f / NTOT));
        float rsv = rsqrtf(var + 1e-5f);
        float gs  = cng[tid] * rsv;
        sxs[tid] = gs;
        sxh[tid] = fmaf(-gs, mu, cnb[tid]);
    }
    __syncthreads();
    #pragma unroll
    for (int i = 0; i < 4; i++) {
        int idx = tid + 512 * i;
        int rr = idx >> 5, c = idx & 31;
        sxn[idx] = fmaf(sxs[c], sxn[idx], sxh[c])
                   + wts[(size_t)(n0 + rr) * CC + c];
    }
    __syncthreads();
    int c = tid & 127, rg = tid >> 7;
    float wreg[CC];
    #pragma unroll
    for (int cin = 0; cin < CC; cin++) wreg[cin] = sW1[cin * CMID + c];
    float bc = b1[c];
    float shsum = 0.f, sh2sum = 0.f;
    for (int i = 0; i < 16; i++) {
        int rr = rg + 4 * i;
        const float4* xr4 = (const float4*)&sxn[rr * CC];
        float a0 = bc, a1 = 0.f;
        #pragma unroll
        for (int q = 0; q < 4; q++) {
            float4 v0 = xr4[q], v1 = xr4[q + 4];
            a0 = fmaf(v0.x, wreg[4*q+0],  a0);
            a1 = fmaf(v1.x, wreg[16+4*q+0], a1);
            a0 = fmaf(v0.y, wreg[4*q+1],  a0);
            a1 = fmaf(v1.y, wreg[16+4*q+1], a1);
            a0 = fmaf(v0.z, wreg[4*q+2],  a0);
            a1 = fmaf(v1.z, wreg[16+4*q+2], a1);
            a0 = fmaf(v0.w, wreg[4*q+3],  a0);
            a1 = fmaf(v1.w, wreg[16+4*q+3], a1);
        }
        float a = a0 + a1;
        float hh = a >= 0.f ? a : 0.01f * a;
        sh[rr * CMID + c] = hh;
        shsum += hh; sh2sum += hh * hh;
    }
    red[tid] = shsum; __syncthreads();
    if (rg == 0) atomicAdd(&g_sh[c], red[c] + red[c + 128] + red[c + 256] + red[c + 384]);
    __syncthreads(); red[tid] = sh2sum; __syncthreads();
    if (rg == 0) atomicAdd(&g_sh2[c], red[c] + red[c + 128] + red[c + 256] + red[c + 384]);
    __threadfence();
    __syncthreads();
    if (tid == 0) {
        atomicAdd(&g_cnth, 1);
        while (*(volatile int*)&g_cnth < HF_GRID) { }
    }
    __syncthreads();
    __threadfence();
    if (tid < CMID) {
        float mu  = g_sh[tid] * (1.f / NTOT);
        float var = fmaf(-mu, mu, g_sh2[tid] * (1.f / NTOT));
        float rsv = rsqrtf(var + 1e-5f);
        float gs  = bng[tid] * rsv;
        shs[tid] = gs;
        shh[tid] = fmaf(-gs, mu, bnb[tid]);
    }
    __syncthreads();
    #pragma unroll
    for (int i = 0; i < 16; i++) {
        int idx = tid + 512 * i;
        int cc = idx & 127;
        sh[idx] = fmaf(shs[cc], sh[idx], shh[cc]);
    }
    __syncthreads();
    int w = tid >> 5, lane = tid & 31;
    float* out_pos = out;
    float* out_w   = out + NTOT * 2;
    #pragma unroll
    for (int r = 0; r < 4; r++) {
        int lr = w * 4 + r;
        int n  = n0 + lr;
        const float* hr = &sh[lr * CMID];
        float acc1 = sb2[lane];
        #pragma unroll 8
        for (int cin = 0; cin < CMID; cin++)
            acc1 = fmaf(hr[cin], sW2[cin * 34 + lane], acc1);
        if (lane < 2) {
            out_pos[n * 2 + lane] = pos[n * 2 + lane] + acc1;
            float acc2 = sb2[32 + lane];
            #pragma unroll 8
            for (int cin = 0; cin < CMID; cin++)
                acc2 = fmaf(hr[cin], sW2[cin * 34 + 32 + lane], acc2);
            out_w[n * CC + 30 + lane] = sxn[lr * CC + 30 + lane] + acc2;
        } else {
            out_w[n * CC + lane - 2] = sxn[lr * CC + lane - 2] + acc1;
        }
    }
}

// ---------------- launch ----------------------------------------------------
extern "C" void kernel_launch(void* const* d_in, const int* in_sizes, int n_in,
                              void* d_out, int out_size) {
    const float* positions = (const float*)d_in[0];
    const float* weights   = (const float*)d_in[1];
    const float* kpos = (const float*)d_in[3];
    const float* kw   = (const float*)d_in[4];
    const float* cng  = (const float*)d_in[5];
    const float* cnb  = (const float*)d_in[6];
    const float* W1   = (const float*)d_in[7];
    const float* b1   = (const float*)d_in[8];
    const float* bng  = (const float*)d_in[9];
    const float* bnb  = (const float*)d_in[10];
    const float* W2   = (const float*)d_in[11];
    const float* b2   = (const float*)d_in[12];
    float* out = (float*)d_out;

    cudaFuncSetAttribute(k_prep, cudaFuncAttributeMaxDynamicSharedMemorySize,
                         PS_WORDS * 4);
    cudaFuncSetAttribute(k_hf, cudaFuncAttributeMaxDynamicSharedMemorySize,
                         HF_FLOATS * 4);
    k_prep<<<128, 256, PS_WORDS * 4>>>(positions, weights, kpos, kw);
    k_main<<<144, 512>>>(positions);
    k_hf<<<HF_GRID, 512, HF_FLOATS * 4>>>(positions, weights, W1, b1,
                                          cng, cnb, bng, bnb, W2, b2, out);
}

// round 16
// speedup vs baseline: 1.0829x; 1.0136x over previous
#include <cuda_runtime.h>
#include <cuda_fp16.h>
#include <cstdint>

#define NTOT 8192
#define BB   8
#define NBAT 1024
#define KK   9
#define CC   32
#define CMID 128
#define MM   9216        // NBAT*KK per batch
#define KSPLIT 9
#define KPART  1024      // MM / KSPLIT
#define NCH    32        // KPART / 32
#define PM_GRID 144
#define HF_GRID 128
#define BSTR   36        // k_main sB row stride in words

// ---------------- scratch (device globals; no allocation anywhere) ----------
__device__ __half  g_convwT[BB * CC * MM];  // [b][c][m], fp16
__device__ float4  g_abxy[BB * MM];         // (am, bx, by, 0) per m
__device__ float   g_part[KSPLIT * NTOT * CC];
__device__ float   g_sx[CC], g_sx2[CC], g_sh[CMID], g_sh2[CMID];
__device__ int     g_cntp;                  // k_pm barrier (monotone ticket)
__device__ int     g_cntx;                  // k_hf barrier 0 (monotone)
__device__ int     g_cnth;                  // k_hf barrier 1 (monotone)

// ---------------- helpers ----------------------------------------------------
__device__ __forceinline__ uint32_t ex2h2(float lo, float hi) {
    uint32_t h2, r;
    asm("cvt.rn.f16x2.f32 %0, %1, %2;" : "=r"(h2) : "f"(hi), "f"(lo));
    asm("ex2.approx.f16x2 %0, %1;" : "=r"(r) : "r"(h2));
    return r;
}
__device__ __forceinline__ uint32_t packh2(float lo, float hi) {
    uint32_t h2;
    asm("cvt.rn.f16x2.f32 %0, %1, %2;" : "=r"(h2) : "f"(hi), "f"(lo));
    return h2;
}
__device__ __forceinline__ void mma_f16(float* d,
                                        uint32_t a0, uint32_t a1,
                                        uint32_t a2, uint32_t a3,
                                        uint32_t b0, uint32_t b1) {
    asm volatile(
        "mma.sync.aligned.m16n8k16.row.col.f32.f16.f16.f32 "
        "{%0,%1,%2,%3}, {%4,%5,%6,%7}, {%8,%9}, {%0,%1,%2,%3};"
        : "+f"(d[0]), "+f"(d[1]), "+f"(d[2]), "+f"(d[3])
        : "r"(a0), "r"(a1), "r"(a2), "r"(a3), "r"(b0), "r"(b1));
}
// Monotone ticket barrier: no reset needed across graph replays.
__device__ __forceinline__ void gbar(int* cnt, int total) {
    __threadfence();
    __syncthreads();
    if (threadIdx.x == 0) {
        int ticket = atomicAdd(cnt, 1);
        int target = (ticket / total + 1) * total;
        while (*(volatile int*)cnt < target) { }
    }
    __syncthreads();
    __threadfence();
}

#define LOG2E 1.4426950408889634f
#define C2    (-2.0f * LOG2E)

// ---------------- K1: fused prep + main --------------------------------------
// grid 144, 512 threads, all-resident.
// Phase A (CTAs 0..127): conv_w fp16 MMA + abxy + stats zeroing (16 warps).
// Ticket barrier (144). Phase B (all): Kmat @ conv_w (verified k_main body).
// dynamic smem (uint32 words): prep layout reused by main after barrier.
#define PS_SKW  0        // 288*20 = 5760  (B: [j][c-pair], fp16)
#define PS_SW   5760     // 64*20  = 1280  (A: [n][c-pair], fp16)
#define PS_ST   7040     // 64*148 = 9472  (out staging: [n][col-pair], fp16)
#define PS_SP   16512    // 128 floats
#define PS_SKP  16640    // 18 floats
#define PS_WORDS 16660   // 66640 bytes
// main-phase aliases (fit easily inside PS_WORDS):
#define PM_SB   0        // 2 * 32*36 = 2304 words
#define PM_SAB  2304     // 2 * 32 float4 = 256 words

__global__ void __launch_bounds__(512) k_pm(const float* __restrict__ pos,
                                            const float* __restrict__ wts,
                                            const float* __restrict__ kpos,
                                            const float* __restrict__ kw) {
    extern __shared__ uint32_t ps[];
    int tid = threadIdx.x;
    // ================= phase A: prep =================
    if (blockIdx.x < 128) {
        uint32_t* skw = ps + PS_SKW;
        uint32_t* sw  = ps + PS_SW;
        uint32_t* st  = ps + PS_ST;
        float*  sp  = (float*)(ps + PS_SP);
        float*  skp = (float*)(ps + PS_SKP);
        __half* skwh = (__half*)skw;
        __half* sth  = (__half*)st;
        int n0 = blockIdx.x * 64;          // global n
        int b  = n0 >> 10;
        int m0 = (n0 & 1023) * KK;         // m within batch
        if (blockIdx.x == 0) {             // re-zero BN stats per replay
            if (tid < CC)   { g_sx[tid] = 0.f; g_sx2[tid] = 0.f; }
            if (tid < CMID) { g_sh[tid] = 0.f; g_sh2[tid] = 0.f; }
        }
        #pragma unroll
        for (int i = 0; i < 2; i++) {
            int wdx = tid + 512 * i;       // 0..1023 (64 rows x 16 pairs)
            int n = wdx >> 4, cp = wdx & 15;
            float2 v = ((const float2*)wts)[(size_t)(n0 + n) * 16 + cp];
            sw[n * 20 + cp] = packh2(v.x, v.y);
        }
        #pragma unroll
        for (int i = 0; i < 18; i++) {
            int flat = tid + 512 * i;      // 0..9215
            int d = flat & 31, c = (flat >> 5) & 31, k = flat >> 10;
            skwh[(k * 32 + d) * 40 + c] = __float2half_rn(kw[flat]);
        }
        if (tid < 128) sp[tid] = pos[n0 * 2 + tid];
        if (tid < KK * 2) skp[tid] = kpos[tid];
        __syncthreads();
        #pragma unroll
        for (int i = 0; i < 2; i++) {
            int idx = tid + 512 * i;
            if (idx < 576) {
                int n = idx / KK, kk2 = idx - KK * (idx / KK);
                float cpx = sp[2 * n]     + skp[2 * kk2];
                float cpy = sp[2 * n + 1] + skp[2 * kk2 + 1];
                float am  = C2 * fmaf(cpx, cpx, cpy * cpy);
                g_abxy[(size_t)b * MM + m0 + idx] =
                    make_float4(am, 4.f * LOG2E * cpx, 4.f * LOG2E * cpy, 0.f);
            }
        }
        int w = tid >> 5, lane = tid & 31;
        int g = lane >> 2, t = lane & 3;
        int wr = w & 3, wc = w >> 2;       // 4 row groups x 4 col groups
        int arow0 = (16 * wr + g) * 20;
        int arow1 = (16 * wr + g + 8) * 20;
        float acc[9][4];
        #pragma unroll
        for (int i = 0; i < 9; i++)
            #pragma unroll
            for (int q = 0; q < 4; q++) acc[i][q] = 0.f;
        #pragma unroll
        for (int s = 0; s < 2; s++) {
            uint32_t a0 = sw[arow0 + t + 8 * s];
            uint32_t a1 = sw[arow1 + t + 8 * s];
            uint32_t a2 = sw[arow0 + t + 8 * s + 4];
            uint32_t a3 = sw[arow1 + t + 8 * s + 4];
            #pragma unroll
            for (int i = 0; i < 9; i++) {
                int brow = (wc * 72 + i * 8 + g) * 20;
                uint32_t b0 = skw[brow + 8 * s + t];
                uint32_t b1 = skw[brow + 8 * s + t + 4];
                mma_f16(acc[i], a0, a1, a2, a3, b0, b1);
            }
        }
        #pragma unroll
        for (int i = 0; i < 9; i++) {
            int cpair = wc * 36 + i * 4 + t;
            st[(16 * wr + g) * 148 + cpair]     = packh2(acc[i][0], acc[i][1]);
            st[(16 * wr + g + 8) * 148 + cpair] = packh2(acc[i][2], acc[i][3]);
        }
        __syncthreads();
        #pragma unroll
        for (int i = 0; i < 18; i++) {
            int flat = tid + 512 * i;      // 0..9215 (288 m-pairs x 32 c)
            int c  = flat / 288;
            int mp = flat - c * 288;
            int mm = 2 * mp;
            int n1 = mm / KK, k1 = mm - KK * n1;
            int mmb = mm + 1;
            int n2 = mmb / KK, k2 = mmb - KK * n2;
            __half v0 = sth[n1 * 296 + k1 * 32 + c];
            __half v1 = sth[n2 * 296 + k2 * 32 + c];
            __half2 pv = __halves2half2(v0, v1);
            *(uint32_t*)((__half*)g_convwT + ((size_t)b * CC + c) * MM + m0 + mm) =
                *(uint32_t*)&pv;
        }
    }
    // ================= barrier =================
    gbar(&g_cntp, PM_GRID);
    // ================= phase B: main (verified body) =================
    uint32_t* sB  = ps + PM_SB;            // [2][32*BSTR]
    float4*   sAB = (float4*)(ps + PM_SAB);// [2][32]
    int w    = tid >> 5, lane = tid & 31;
    int g    = lane >> 2, t = lane & 3;
    int blk  = blockIdx.x;
    int b   = blk / 18;
    int rem = blk - b * 18;
    int rb  = rem / 9;
    int ks  = rem - rb * 9;
    int ctabase = b * NBAT + rb * 512;
    int rbase   = ctabase + w * 32;
    size_t mbase = (size_t)b * MM + (size_t)ks * KPART;

    int sc = tid >> 3, sq = tid & 7;
    const uint2* gB = (const uint2*)(g_convwT + ((size_t)b * CC + sc) * MM
                                     + (size_t)ks * KPART);
    const float4* gAB = g_abxy + mbase;

    float px[4], py[4], pp[4];
    #pragma unroll
    for (int u = 0; u < 4; u++) {
        float2 p = ((const float2*)pos)[rbase + g + 8 * u];
        px[u] = p.x; py[u] = p.y;
        pp[u] = C2 * fmaf(p.x, p.x, p.y * p.y);
    }
    float acc[2][4][4];
    #pragma unroll
    for (int j = 0; j < 2; j++)
        #pragma unroll
        for (int i = 0; i < 4; i++)
            #pragma unroll
            for (int q = 0; q < 4; q++) acc[j][i][q] = 0.f;

    if (tid < 256) {
        uint2 v = gB[sq];
        sB[sc * BSTR + sq * 2]     = v.x;
        sB[sc * BSTR + sq * 2 + 1] = v.y;
    }
    if (tid < 32) sAB[tid] = gAB[tid];
    for (int tc = 0; tc < NCH; tc++) {
        int buf = tc & 1;
        __syncthreads();
        if (tc + 1 < NCH) {
            if (tid < 256) {
                uint2 v = gB[(tc + 1) * 8 + sq];
                sB[(buf ^ 1) * (32 * BSTR) + sc * BSTR + sq * 2]     = v.x;
                sB[(buf ^ 1) * (32 * BSTR) + sc * BSTR + sq * 2 + 1] = v.y;
            }
            if (tid < 32) sAB[(buf ^ 1) * 32 + tid] = gAB[(tc + 1) * 32 + tid];
        }
        uint32_t A16[4][4];
        #pragma unroll
        for (int v = 0; v < 4; v++) {
            float4 qa = sAB[buf * 32 + 2 * t + 8 * v];
            float4 qb = sAB[buf * 32 + 2 * t + 8 * v + 1];
            #pragma unroll
            for (int u = 0; u < 4; u++) {
                float lo = fmaf(qa.y, px[u], fmaf(qa.z, py[u], pp[u] + qa.x));
                float hi = fmaf(qb.y, px[u], fmaf(qb.z, py[u], pp[u] + qb.x));
                A16[u][v] = ex2h2(lo, hi);
            }
        }
        #pragma unroll
        for (int i = 0; i < 4; i++) {
            int base = buf * (32 * BSTR) + (i * 8 + g) * BSTR;
            #pragma unroll
            for (int s = 0; s < 2; s++) {
                uint32_t b0 = sB[base + 8 * s + t];
                uint32_t b1 = sB[base + 8 * s + t + 4];
                #pragma unroll
                for (int j = 0; j < 2; j++)
                    mma_f16(acc[j][i],
                            A16[2*j][2*s],   A16[2*j+1][2*s],
                            A16[2*j][2*s+1], A16[2*j+1][2*s+1],
                            b0, b1);
            }
        }
    }
    #pragma unroll
    for (int j = 0; j < 2; j++) {
        int nr0 = rbase + j * 16 + g;
        #pragma unroll
        for (int i = 0; i < 4; i++) {
            int c = i * 8 + t * 2;
            *(float2*)&g_part[((size_t)ks * NTOT + nr0) * CC + c] =
                make_float2(acc[j][i][0], acc[j][i][1]);
            *(float2*)&g_part[((size_t)ks * NTOT + nr0 + 8) * CC + c] =
                make_float2(acc[j][i][2], acc[j][i][3]);
        }
    }
}

// ---------------- K2: reduce -> x-stats -> xn -> h -> BN(h) -> W2 -> out ----
// grid 128, 512 threads; 64 rows/block; ticket barriers (no reset needed).
#define HF_SXN  0        // 64*32   = 2048
#define HF_SW1  2048     // 32*128  = 4096
#define HF_SH   6144     // 64*128  = 8192
#define HF_SW2  14336    // 128*34  = 4352
#define HF_SB2  18688    // 48
#define HF_SXS  18736    // 32
#define HF_SXH  18768    // 32
#define HF_SHS  18800    // 128
#define HF_SHH  18928    // 128
#define HF_RED  19056    // 512
#define HF_FLOATS 19568  // 78272 bytes

__global__ void __launch_bounds__(512) k_hf(const float* __restrict__ pos,
                                            const float* __restrict__ wts,
                                            const float* __restrict__ W1,
                                            const float* __restrict__ b1,
                                            const float* __restrict__ cng,
                                            const float* __restrict__ cnb,
                                            const float* __restrict__ bng,
                                            const float* __restrict__ bnb,
                                            const float* __restrict__ W2,
                                            const float* __restrict__ b2,
                                            float* __restrict__ out) {
    extern __shared__ float dyn[];
    float* sxn = dyn + HF_SXN;
    float* sW1 = dyn + HF_SW1;
    float* sh  = dyn + HF_SH;
    float* sW2 = dyn + HF_SW2;
    float* sb2 = dyn + HF_SB2;
    float* sxs = dyn + HF_SXS;
    float* sxh = dyn + HF_SXH;
    float* shs = dyn + HF_SHS;
    float* shh = dyn + HF_SHH;
    float* red = dyn + HF_RED;
    int tid = threadIdx.x;
    int n0 = blockIdx.x * 64;
    #pragma unroll
    for (int i = 0; i < 8; i++) sW1[tid + 512 * i] = W1[tid + 512 * i];
    for (int i = tid; i < CMID * 34; i += 512) sW2[i] = W2[i];
    if (tid < 34) sb2[tid] = b2[tid];
    // ---- phase 0: reduce KSPLIT partials, leaky, local x into smem ----
    {
        int n = tid >> 3, c4 = (tid & 7) * 4;
        const float4* base = (const float4*)(g_part
                              + (size_t)(n0 + n) * CC + c4);
        float4 a = base[0];
        #pragma unroll
        for (int s = 1; s < KSPLIT; s++) {
            float4 v = base[(size_t)s * (NTOT * CC / 4)];
            a.x += v.x; a.y += v.y; a.z += v.z; a.w += v.w;
        }
        a.x = a.x >= 0.f ? a.x : 0.01f * a.x;
        a.y = a.y >= 0.f ? a.y : 0.01f * a.y;
        a.z = a.z >= 0.f ? a.z : 0.01f * a.z;
        a.w = a.w >= 0.f ? a.w : 0.01f * a.w;
        *(float4*)&sxn[n * CC + c4] = a;
    }
    __syncthreads();
    {
        int c = tid & 31, rs = tid >> 5;
        float sx = 0.f, sx2 = 0.f;
        #pragma unroll
        for (int i = 0; i < 4; i++) {
            float v = sxn[(rs + 16 * i) * CC + c];
            sx += v; sx2 += v * v;
        }
        red[tid] = sx; __syncthreads();
        if (rs == 0) {
            float s = 0.f;
            #pragma unroll
            for (int j = 0; j < 16; j++) s += red[c + 32 * j];
            atomicAdd(&g_sx[c], s);
        }
        __syncthreads(); red[tid] = sx2; __syncthreads();
        if (rs == 0) {
            float s = 0.f;
            #pragma unroll
            for (int j = 0; j < 16; j++) s += red[c + 32 * j];
            atomicAdd(&g_sx2[c], s);
        }
    }
    gbar(&g_cntx, HF_GRID);
    if (tid < CC) {
        float mu  = g_sx[tid] * (1.f / NTOT);
        float var = fmaf(-mu, mu, g_sx2[tid] * (1.f / NTOT));
        float rsv = rsqrtf(var + 1e-5f);
        float gs  = cng[tid] * rsv;
        sxs[tid] = gs;
        sxh[tid] = fmaf(-gs, mu, cnb[tid]);
    }
    __syncthreads();
    #pragma unroll
    for (int i = 0; i < 4; i++) {
        int idx = tid + 512 * i;
        int rr = idx >> 5, c = idx & 31;
        sxn[idx] = fmaf(sxs[c], sxn[idx], sxh[c])
                   + wts[(size_t)(n0 + rr) * CC + c];
    }
    __syncthreads();
    int c = tid & 127, rg = tid >> 7;
    float wreg[CC];
    #pragma unroll
    for (int cin = 0; cin < CC; cin++) wreg[cin] = sW1[cin * CMID + c];
    float bc = b1[c];
    float shsum = 0.f, sh2sum = 0.f;
    for (int i = 0; i < 16; i++) {
        int rr = rg + 4 * i;
        const float4* xr4 = (const float4*)&sxn[rr * CC];
        float a0 = bc, a1 = 0.f;
        #pragma unroll
        for (int q = 0; q < 4; q++) {
            float4 v0 = xr4[q], v1 = xr4[q + 4];
            a0 = fmaf(v0.x, wreg[4*q+0],  a0);
            a1 = fmaf(v1.x, wreg[16+4*q+0], a1);
            a0 = fmaf(v0.y, wreg[4*q+1],  a0);
            a1 = fmaf(v1.y, wreg[16+4*q+1], a1);
            a0 = fmaf(v0.z, wreg[4*q+2],  a0);
            a1 = fmaf(v1.z, wreg[16+4*q+2], a1);
            a0 = fmaf(v0.w, wreg[4*q+3],  a0);
            a1 = fmaf(v1.w, wreg[16+4*q+3], a1);
        }
        float a = a0 + a1;
        float hh = a >= 0.f ? a : 0.01f * a;
        sh[rr * CMID + c] = hh;
        shsum += hh; sh2sum += hh * hh;
    }
    red[tid] = shsum; __syncthreads();
    if (rg == 0) atomicAdd(&g_sh[c], red[c] + red[c + 128] + red[c + 256] + red[c + 384]);
    __syncthreads(); red[tid] = sh2sum; __syncthreads();
    if (rg == 0) atomicAdd(&g_sh2[c], red[c] + red[c + 128] + red[c + 256] + red[c + 384]);
    gbar(&g_cnth, HF_GRID);
    if (tid < CMID) {
        float mu  = g_sh[tid] * (1.f / NTOT);
        float var = fmaf(-mu, mu, g_sh2[tid] * (1.f / NTOT));
        float rsv = rsqrtf(var + 1e-5f);
        float gs  = bng[tid] * rsv;
        shs[tid] = gs;
        shh[tid] = fmaf(-gs, mu, bnb[tid]);
    }
    __syncthreads();
    #pragma unroll
    for (int i = 0; i < 16; i++) {
        int idx = tid + 512 * i;
        int cc = idx & 127;
        sh[idx] = fmaf(shs[cc], sh[idx], shh[cc]);
    }
    __syncthreads();
    int w = tid >> 5, lane = tid & 31;
    float* out_pos = out;
    float* out_w   = out + NTOT * 2;
    #pragma unroll
    for (int r = 0; r < 4; r++) {
        int lr = w * 4 + r;
        int n  = n0 + lr;
        const float* hr = &sh[lr * CMID];
        float acc1 = sb2[lane];
        #pragma unroll 8
        for (int cin = 0; cin < CMID; cin++)
            acc1 = fmaf(hr[cin], sW2[cin * 34 + lane], acc1);
        if (lane < 2) {
            out_pos[n * 2 + lane] = pos[n * 2 + lane] + acc1;
            float acc2 = sb2[32 + lane];
            #pragma unroll 8
            for (int cin = 0; cin < CMID; cin++)
                acc2 = fmaf(hr[cin], sW2[cin * 34 + 32 + lane], acc2);
            out_w[n * CC + 30 + lane] = sxn[lr * CC + 30 + lane] + acc2;
        } else {
            out_w[n * CC + lane - 2] = sxn[lr * CC + lane - 2] + acc1;
        }
    }
}

// ---------------- launch ----------------------------------------------------
extern "C" void kernel_launch(void* const* d_in, const int* in_sizes, int n_in,
                              void* d_out, int out_size) {
    const float* positions = (const float*)d_in[0];
    const float* weights   = (const float*)d_in[1];
    const float* kpos = (const float*)d_in[3];
    const float* kw   = (const float*)d_in[4];
    const float* cng  = (const float*)d_in[5];
    const float* cnb  = (const float*)d_in[6];
    const float* W1   = (const float*)d_in[7];
    const float* b1   = (const float*)d_in[8];
    const float* bng  = (const float*)d_in[9];
    const float* bnb  = (const float*)d_in[10];
    const float* W2   = (const float*)d_in[11];
    const float* b2   = (const float*)d_in[12];
    float* out = (float*)d_out;

    cudaFuncSetAttribute(k_pm, cudaFuncAttributeMaxDynamicSharedMemorySize,
                         PS_WORDS * 4);
    cudaFuncSetAttribute(k_hf, cudaFuncAttributeMaxDynamicSharedMemorySize,
                         HF_FLOATS * 4);
    k_pm<<<PM_GRID, 512, PS_WORDS * 4>>>(positions, weights, kpos, kw);
    k_hf<<<HF_GRID, 512, HF_FLOATS * 4>>>(positions, weights, W1, b1,
                                          cng, cnb, bng, bnb, W2, b2, out);
}

// round 17
// speedup vs baseline: 1.0834x; 1.0005x over previous
#include <cuda_runtime.h>
#include <cuda_fp16.h>
#include <cstdint>

#define NTOT 8192
#define BB   8
#define NBAT 1024
#define KK   9
#define CC   32
#define CMID 128
#define MM   9216        // NBAT*KK per batch
#define KSPLIT 9
#define KPART  1024      // MM / KSPLIT
#define NCH    32        // KPART / 32
#define HF_GRID 128
#define BSTR   36        // k_main sB row stride in words

// ---------------- scratch (device globals; no allocation anywhere) ----------
__device__ __half  g_convwT[BB * CC * MM];  // [b][c][m], fp16
__device__ float4  g_abxy[BB * MM];         // (am, bx, by, 0) per m
__device__ float   g_part[KSPLIT * NTOT * CC];
__device__ float   g_sx[CC], g_sx2[CC], g_sh[CMID], g_sh2[CMID];
__device__ int     g_cntx;                  // k_hf barrier 0 (monotone ticket)
__device__ int     g_cnth;                  // k_hf barrier 1 (monotone ticket)

// ---------------- helpers ----------------------------------------------------
__device__ __forceinline__ uint32_t ex2h2(float lo, float hi) {
    uint32_t h2, r;
    asm("cvt.rn.f16x2.f32 %0, %1, %2;" : "=r"(h2) : "f"(hi), "f"(lo));
    asm("ex2.approx.f16x2 %0, %1;" : "=r"(r) : "r"(h2));
    return r;
}
__device__ __forceinline__ uint32_t packh2(float lo, float hi) {
    uint32_t h2;
    asm("cvt.rn.f16x2.f32 %0, %1, %2;" : "=r"(h2) : "f"(hi), "f"(lo));
    return h2;
}
__device__ __forceinline__ void mma_f16(float* d,
                                        uint32_t a0, uint32_t a1,
                                        uint32_t a2, uint32_t a3,
                                        uint32_t b0, uint32_t b1) {
    asm volatile(
        "mma.sync.aligned.m16n8k16.row.col.f32.f16.f16.f32 "
        "{%0,%1,%2,%3}, {%4,%5,%6,%7}, {%8,%9}, {%0,%1,%2,%3};"
        : "+f"(d[0]), "+f"(d[1]), "+f"(d[2]), "+f"(d[3])
        : "r"(a0), "r"(a1), "r"(a2), "r"(a3), "r"(b0), "r"(b1));
}
// Monotone ticket barrier: no reset needed across graph replays.
__device__ __forceinline__ void gbar(int* cnt, int total) {
    __threadfence();
    __syncthreads();
    if (threadIdx.x == 0) {
        int ticket = atomicAdd(cnt, 1);
        int target = (ticket / total + 1) * total;
        while (*(volatile int*)cnt < target) { }
    }
    __syncthreads();
    __threadfence();
}

#define LOG2E 1.4426950408889634f
#define C2    (-2.0f * LOG2E)

// ---------------- K1: conv_w via fp16 MMA + abxy + zero stats ---------------
// grid 128 (64 n per block), 256 threads (Round-13 verified)
#define PS_SKW  0        // 288*20 = 5760  (B: [j][c-pair], fp16)
#define PS_SW   5760     // 64*20  = 1280  (A: [n][c-pair], fp16)
#define PS_ST   7040     // 64*148 = 9472  (out staging: [n][col-pair], fp16)
#define PS_SP   16512    // 128 floats
#define PS_SKP  16640    // 18 floats
#define PS_WORDS 16660   // 66640 bytes

__global__ void __launch_bounds__(256) k_prep(const float* __restrict__ pos,
                                              const float* __restrict__ wts,
                                              const float* __restrict__ kpos,
                                              const float* __restrict__ kw) {
    extern __shared__ uint32_t ps[];
    uint32_t* skw = ps + PS_SKW;
    uint32_t* sw  = ps + PS_SW;
    uint32_t* st  = ps + PS_ST;
    float*  sp  = (float*)(ps + PS_SP);
    float*  skp = (float*)(ps + PS_SKP);
    __half* skwh = (__half*)skw;
    __half* sth  = (__half*)st;
    int tid = threadIdx.x;
    int n0 = blockIdx.x * 64;          // global n
    int b  = n0 >> 10;
    int m0 = (n0 & 1023) * KK;         // m within batch
    if (blockIdx.x == 0) {             // re-zero BN stats per replay
        if (tid < CC)   { g_sx[tid] = 0.f; g_sx2[tid] = 0.f; }
        if (tid < CMID) { g_sh[tid] = 0.f; g_sh2[tid] = 0.f; }
    }
    #pragma unroll
    for (int i = 0; i < 4; i++) {
        int wdx = tid + 256 * i;       // 0..1023 (64 rows x 16 pairs)
        int n = wdx >> 4, cp = wdx & 15;
        float2 v = ((const float2*)wts)[(size_t)(n0 + n) * 16 + cp];
        sw[n * 20 + cp] = packh2(v.x, v.y);
    }
    #pragma unroll
    for (int i = 0; i < 36; i++) {
        int flat = tid + 256 * i;      // 0..9215
        int d = flat & 31, c = (flat >> 5) & 31, k = flat >> 10;
        skwh[(k * 32 + d) * 40 + c] = __float2half_rn(kw[flat]);
    }
    if (tid < 128) sp[tid] = pos[n0 * 2 + tid];
    if (tid < KK * 2) skp[tid] = kpos[tid];
    __syncthreads();
    #pragma unroll
    for (int i = 0; i < 3; i++) {
        int idx = tid + 256 * i;
        if (idx < 576) {
            int n = idx / KK, kk2 = idx - KK * (idx / KK);
            float cpx = sp[2 * n]     + skp[2 * kk2];
            float cpy = sp[2 * n + 1] + skp[2 * kk2 + 1];
            float am  = C2 * fmaf(cpx, cpx, cpy * cpy);
            g_abxy[(size_t)b * MM + m0 + idx] =
                make_float4(am, 4.f * LOG2E * cpx, 4.f * LOG2E * cpy, 0.f);
        }
    }
    int w = tid >> 5, lane = tid & 31;
    int g = lane >> 2, t = lane & 3;
    int wr = w & 3, wc = w >> 2;
    int arow0 = (16 * wr + g) * 20;
    int arow1 = (16 * wr + g + 8) * 20;
    float acc[18][4];
    #pragma unroll
    for (int i = 0; i < 18; i++)
        #pragma unroll
        for (int q = 0; q < 4; q++) acc[i][q] = 0.f;
    #pragma unroll
    for (int s = 0; s < 2; s++) {
        uint32_t a0 = sw[arow0 + t + 8 * s];
        uint32_t a1 = sw[arow1 + t + 8 * s];
        uint32_t a2 = sw[arow0 + t + 8 * s + 4];
        uint32_t a3 = sw[arow1 + t + 8 * s + 4];
        #pragma unroll
        for (int i = 0; i < 18; i++) {
            int brow = (wc * 144 + i * 8 + g) * 20;
            uint32_t b0 = skw[brow + 8 * s + t];
            uint32_t b1 = skw[brow + 8 * s + t + 4];
            mma_f16(acc[i], a0, a1, a2, a3, b0, b1);
        }
    }
    #pragma unroll
    for (int i = 0; i < 18; i++) {
        int cpair = wc * 72 + i * 4 + t;
        st[(16 * wr + g) * 148 + cpair]     = packh2(acc[i][0], acc[i][1]);
        st[(16 * wr + g + 8) * 148 + cpair] = packh2(acc[i][2], acc[i][3]);
    }
    __syncthreads();
    #pragma unroll
    for (int i = 0; i < 36; i++) {
        int flat = tid + 256 * i;      // 0..9215 (288 m-pairs x 32 c)
        int c  = flat / 288;
        int mp = flat - c * 288;
        int mm = 2 * mp;
        int n1 = mm / KK, k1 = mm - KK * n1;
        int mmb = mm + 1;
        int n2 = mmb / KK, k2 = mmb - KK * n2;
        __half v0 = sth[n1 * 296 + k1 * 32 + c];
        __half v1 = sth[n2 * 296 + k2 * 32 + c];
        __half2 pv = __halves2half2(v0, v1);
        *(uint32_t*)((__half*)g_convwT + ((size_t)b * CC + c) * MM + m0 + mm) =
            *(uint32_t*)&pv;
    }
}

// ---------------- K2: Kmat @ conv_w via mma.sync fp16 (Round-13 verified) ---
__global__ void __launch_bounds__(512) k_main(const float* __restrict__ pos) {
    __shared__ uint32_t sB[2][32 * BSTR];
    __shared__ float4   sAB[2][32];
    int tid  = threadIdx.x;
    int w    = tid >> 5, lane = tid & 31;
    int g    = lane >> 2, t = lane & 3;
    int blk  = blockIdx.x;
    int b   = blk / 18;
    int rem = blk - b * 18;
    int rb  = rem / 9;
    int ks  = rem - rb * 9;
    int ctabase = b * NBAT + rb * 512;
    int rbase   = ctabase + w * 32;
    size_t mbase = (size_t)b * MM + (size_t)ks * KPART;

    int sc = tid >> 3, sq = tid & 7;
    const uint2* gB = (const uint2*)(g_convwT + ((size_t)b * CC + sc) * MM
                                     + (size_t)ks * KPART);
    const float4* gAB = g_abxy + mbase;

    float px[4], py[4], pp[4];
    #pragma unroll
    for (int u = 0; u < 4; u++) {
        float2 p = ((const float2*)pos)[rbase + g + 8 * u];
        px[u] = p.x; py[u] = p.y;
        pp[u] = C2 * fmaf(p.x, p.x, p.y * p.y);
    }
    float acc[2][4][4];
    #pragma unroll
    for (int j = 0; j < 2; j++)
        #pragma unroll
        for (int i = 0; i < 4; i++)
            #pragma unroll
            for (int q = 0; q < 4; q++) acc[j][i][q] = 0.f;

    if (tid < 256) {
        uint2 v = gB[sq];
        sB[0][sc * BSTR + sq * 2]     = v.x;
        sB[0][sc * BSTR + sq * 2 + 1] = v.y;
    }
    if (tid < 32) sAB[0][tid] = gAB[tid];
    for (int tc = 0; tc < NCH; tc++) {
        int buf = tc & 1;
        __syncthreads();
        if (tc + 1 < NCH) {
            if (tid < 256) {
                uint2 v = gB[(tc + 1) * 8 + sq];
                sB[buf ^ 1][sc * BSTR + sq * 2]     = v.x;
                sB[buf ^ 1][sc * BSTR + sq * 2 + 1] = v.y;
            }
            if (tid < 32) sAB[buf ^ 1][tid] = gAB[(tc + 1) * 32 + tid];
        }
        uint32_t A16[4][4];
        #pragma unroll
        for (int v = 0; v < 4; v++) {
            float4 qa = sAB[buf][2 * t + 8 * v];
            float4 qb = sAB[buf][2 * t + 8 * v + 1];
            #pragma unroll
            for (int u = 0; u < 4; u++) {
                float lo = fmaf(qa.y, px[u], fmaf(qa.z, py[u], pp[u] + qa.x));
                float hi = fmaf(qb.y, px[u], fmaf(qb.z, py[u], pp[u] + qb.x));
                A16[u][v] = ex2h2(lo, hi);
            }
        }
        #pragma unroll
        for (int i = 0; i < 4; i++) {
            int base = (i * 8 + g) * BSTR;
            #pragma unroll
            for (int s = 0; s < 2; s++) {
                uint32_t b0 = sB[buf][base + 8 * s + t];
                uint32_t b1 = sB[buf][base + 8 * s + t + 4];
                #pragma unroll
                for (int j = 0; j < 2; j++)
                    mma_f16(acc[j][i],
                            A16[2*j][2*s],   A16[2*j+1][2*s],
                            A16[2*j][2*s+1], A16[2*j+1][2*s+1],
                            b0, b1);
            }
        }
    }
    #pragma unroll
    for (int j = 0; j < 2; j++) {
        int nr0 = rbase + j * 16 + g;
        #pragma unroll
        for (int i = 0; i < 4; i++) {
            int c = i * 8 + t * 2;
            *(float2*)&g_part[((size_t)ks * NTOT + nr0) * CC + c] =
                make_float2(acc[j][i][0], acc[j][i][1]);
            *(float2*)&g_part[((size_t)ks * NTOT + nr0 + 8) * CC + c] =
                make_float2(acc[j][i][2], acc[j][i][3]);
        }
    }
}

// ---------------- K3: reduce -> x-stats -> xn -> h(MMA) -> BN(h) -> W2 ------
// grid 128, 512 threads; 64 rows/block; ticket barriers.
#define HF_SXN   0       // 64*32  = 2048
#define HF_SXNH  2048    // 64*20  = 1280 words (fp16 A tile)
#define HF_SW1H  3328    // 128*20 = 2560 words (fp16 B = W1^T)
#define HF_SH    5888    // 64*128 = 8192
#define HF_SW2   14080   // 128*34 = 4352
#define HF_SB1   18432   // 128
#define HF_SB2   18560   // 48
#define HF_SXS   18608   // 32
#define HF_SXH   18640   // 32
#define HF_SHS   18672   // 128
#define HF_SHH   18800   // 128
#define HF_RED   18928   // 512
#define HF_FLOATS 19440  // 77760 bytes

__global__ void __launch_bounds__(512) k_hf(const float* __restrict__ pos,
                                            const float* __restrict__ wts,
                                            const float* __restrict__ W1,
                                            const float* __restrict__ b1,
                                            const float* __restrict__ cng,
                                            const float* __restrict__ cnb,
                                            const float* __restrict__ bng,
                                            const float* __restrict__ bnb,
                                            const float* __restrict__ W2,
                                            const float* __restrict__ b2,
                                            float* __restrict__ out) {
    extern __shared__ float dyn[];
    float*    sxn  = dyn + HF_SXN;
    uint32_t* sxnh = (uint32_t*)(dyn + HF_SXNH);
    uint32_t* sW1h = (uint32_t*)(dyn + HF_SW1H);
    float*    sh   = dyn + HF_SH;
    float*    sW2  = dyn + HF_SW2;
    float*    sb1  = dyn + HF_SB1;
    float*    sb2  = dyn + HF_SB2;
    float*    sxs  = dyn + HF_SXS;
    float*    sxh  = dyn + HF_SXH;
    float*    shs  = dyn + HF_SHS;
    float*    shh  = dyn + HF_SHH;
    float*    red  = dyn + HF_RED;
    __half*   sW1hh = (__half*)sW1h;
    int tid = threadIdx.x;
    int n0 = blockIdx.x * 64;
    // weight staging (overlaps phase 0)
    #pragma unroll
    for (int i = 0; i < 8; i++) {
        int flat = tid + 512 * i;          // 0..4095; W1[cin][outc]
        int cin = flat >> 7, outc = flat & 127;
        sW1hh[outc * 40 + cin] = __float2half_rn(W1[flat]);
    }
    for (int i = tid; i < CMID * 34; i += 512) sW2[i] = W2[i];
    if (tid < CMID) sb1[tid] = b1[tid];
    if (tid < 34) sb2[tid] = b2[tid];
    // ---- phase 0: reduce KSPLIT partials, leaky, local x into smem ----
    {
        int n = tid >> 3, c4 = (tid & 7) * 4;
        const float4* base = (const float4*)(g_part
                              + (size_t)(n0 + n) * CC + c4);
        float4 a = base[0];
        #pragma unroll
        for (int s = 1; s < KSPLIT; s++) {
            float4 v = base[(size_t)s * (NTOT * CC / 4)];
            a.x += v.x; a.y += v.y; a.z += v.z; a.w += v.w;
        }
        a.x = a.x >= 0.f ? a.x : 0.01f * a.x;
        a.y = a.y >= 0.f ? a.y : 0.01f * a.y;
        a.z = a.z >= 0.f ? a.z : 0.01f * a.z;
        a.w = a.w >= 0.f ? a.w : 0.01f * a.w;
        *(float4*)&sxn[n * CC + c4] = a;
    }
    __syncthreads();
    {
        int c = tid & 31, rs = tid >> 5;
        float sx = 0.f, sx2 = 0.f;
        #pragma unroll
        for (int i = 0; i < 4; i++) {
            float v = sxn[(rs + 16 * i) * CC + c];
            sx += v; sx2 += v * v;
        }
        red[tid] = sx; __syncthreads();
        if (rs == 0) {
            float s = 0.f;
            #pragma unroll
            for (int j = 0; j < 16; j++) s += red[c + 32 * j];
            atomicAdd(&g_sx[c], s);
        }
        __syncthreads(); red[tid] = sx2; __syncthreads();
        if (rs == 0) {
            float s = 0.f;
            #pragma unroll
            for (int j = 0; j < 16; j++) s += red[c + 32 * j];
            atomicAdd(&g_sx2[c], s);
        }
    }
    gbar(&g_cntx, HF_GRID);
    if (tid < CC) {
        float mu  = g_sx[tid] * (1.f / NTOT);
        float var = fmaf(-mu, mu, g_sx2[tid] * (1.f / NTOT));
        float rsv = rsqrtf(var + 1e-5f);
        float gs  = cng[tid] * rsv;
        sxs[tid] = gs;
        sxh[tid] = fmaf(-gs, mu, cnb[tid]);
    }
    __syncthreads();
    // xn in place (fp32)
    #pragma unroll
    for (int i = 0; i < 4; i++) {
        int idx = tid + 512 * i;
        int rr = idx >> 5, c = idx & 31;
        sxn[idx] = fmaf(sxs[c], sxn[idx], sxh[c])
                   + wts[(size_t)(n0 + rr) * CC + c];
    }
    __syncthreads();
    // pack xn to fp16 A tile
    #pragma unroll
    for (int i = 0; i < 2; i++) {
        int idx = tid + 512 * i;           // 0..1023 (64 rows x 16 pairs)
        int n = idx >> 4, cp = idx & 15;
        sxnh[n * 20 + cp] = packh2(sxn[n * CC + 2 * cp], sxn[n * CC + 2 * cp + 1]);
    }
    __syncthreads();
    // h = leaky(xn @ W1 + b1) via fp16 MMA; 16 warps = 4 row x 4 col groups
    {
        int w = tid >> 5, lane = tid & 31;
        int g = lane >> 2, t = lane & 3;
        int wr = w & 3, wc = w >> 2;
        int arow0 = (16 * wr + g) * 20;
        int arow1 = (16 * wr + g + 8) * 20;
        float hacc[4][4];
        #pragma unroll
        for (int i = 0; i < 4; i++)
            #pragma unroll
            for (int q = 0; q < 4; q++) hacc[i][q] = 0.f;
        #pragma unroll
        for (int s = 0; s < 2; s++) {
            uint32_t a0 = sxnh[arow0 + 8 * s + t];
            uint32_t a1 = sxnh[arow1 + 8 * s + t];
            uint32_t a2 = sxnh[arow0 + 8 * s + t + 4];
            uint32_t a3 = sxnh[arow1 + 8 * s + t + 4];
            #pragma unroll
            for (int i = 0; i < 4; i++) {
                int brow = (wc * 32 + i * 8 + g) * 20;
                uint32_t b0 = sW1h[brow + 8 * s + t];
                uint32_t b1v = sW1h[brow + 8 * s + t + 4];
                mma_f16(hacc[i], a0, a1, a2, a3, b0, b1v);
            }
        }
        #pragma unroll
        for (int i = 0; i < 4; i++) {
            int col = wc * 32 + i * 8 + 2 * t;
            float bA = sb1[col], bB = sb1[col + 1];
            float v0 = hacc[i][0] + bA, v1 = hacc[i][1] + bB;
            float v2 = hacc[i][2] + bA, v3 = hacc[i][3] + bB;
            v0 = v0 >= 0.f ? v0 : 0.01f * v0;
            v1 = v1 >= 0.f ? v1 : 0.01f * v1;
            v2 = v2 >= 0.f ? v2 : 0.01f * v2;
            v3 = v3 >= 0.f ? v3 : 0.01f * v3;
            sh[(16 * wr + g) * CMID + col]         = v0;
            sh[(16 * wr + g) * CMID + col + 1]     = v1;
            sh[(16 * wr + g + 8) * CMID + col]     = v2;
            sh[(16 * wr + g + 8) * CMID + col + 1] = v3;
        }
    }
    __syncthreads();
    // h-stats pass
    {
        int c = tid & 127, rg = tid >> 7;
        float shsum = 0.f, sh2sum = 0.f;
        #pragma unroll
        for (int i = 0; i < 16; i++) {
            float v = sh[(rg + 4 * i) * CMID + c];
            shsum += v; sh2sum += v * v;
        }
        red[tid] = shsum; __syncthreads();
        if (rg == 0) atomicAdd(&g_sh[c], red[c] + red[c + 128] + red[c + 256] + red[c + 384]);
        __syncthreads(); red[tid] = sh2sum; __syncthreads();
        if (rg == 0) atomicAdd(&g_sh2[c], red[c] + red[c + 128] + red[c + 256] + red[c + 384]);
    }
    gbar(&g_cnth, HF_GRID);
    if (tid < CMID) {
        float mu  = g_sh[tid] * (1.f / NTOT);
        float var = fmaf(-mu, mu, g_sh2[tid] * (1.f / NTOT));
        float rsv = rsqrtf(var + 1e-5f);
        float gs  = bng[tid] * rsv;
        shs[tid] = gs;
        shh[tid] = fmaf(-gs, mu, bnb[tid]);
    }
    __syncthreads();
    #pragma unroll
    for (int i = 0; i < 16; i++) {
        int idx = tid + 512 * i;
        int cc = idx & 127;
        sh[idx] = fmaf(shs[cc], sh[idx], shh[cc]);
    }
    __syncthreads();
    int w = tid >> 5, lane = tid & 31;
    float* out_pos = out;
    float* out_w   = out + NTOT * 2;
    #pragma unroll
    for (int r = 0; r < 4; r++) {
        int lr = w * 4 + r;
        int n  = n0 + lr;
        const float* hr = &sh[lr * CMID];
        float acc1 = sb2[lane];
        #pragma unroll 8
        for (int cin = 0; cin < CMID; cin++)
            acc1 = fmaf(hr[cin], sW2[cin * 34 + lane], acc1);
        if (lane < 2) {
            out_pos[n * 2 + lane] = pos[n * 2 + lane] + acc1;
            float acc2 = sb2[32 + lane];
            #pragma unroll 8
            for (int cin = 0; cin < CMID; cin++)
                acc2 = fmaf(hr[cin], sW2[cin * 34 + 32 + lane], acc2);
            out_w[n * CC + 30 + lane] = sxn[lr * CC + 30 + lane] + acc2;
        } else {
            out_w[n * CC + lane - 2] = sxn[lr * CC + lane - 2] + acc1;
        }
    }
}

// ---------------- launch ----------------------------------------------------
extern "C" void kernel_launch(void* const* d_in, const int* in_sizes, int n_in,
                              void* d_out, int out_size) {
    const float* positions = (const float*)d_in[0];
    const float* weights   = (const float*)d_in[1];
    const float* kpos = (const float*)d_in[3];
    const float* kw   = (const float*)d_in[4];
    const float* cng  = (const float*)d_in[5];
    const float* cnb  = (const float*)d_in[6];
    const float* W1   = (const float*)d_in[7];
    const float* b1   = (const float*)d_in[8];
    const float* bng  = (const float*)d_in[9];
    const float* bnb  = (const float*)d_in[10];
    const float* W2   = (const float*)d_in[11];
    const float* b2   = (const float*)d_in[12];
    float* out = (float*)d_out;

    cudaFuncSetAttribute(k_prep, cudaFuncAttributeMaxDynamicSharedMemorySize,
                         PS_WORDS * 4);
    cudaFuncSetAttribute(k_hf, cudaFuncAttributeMaxDynamicSharedMemorySize,
                         HF_FLOATS * 4);
    k_prep<<<128, 256, PS_WORDS * 4>>>(positions, weights, kpos, kw);
    k_main<<<144, 512>>>(positions);
    k_hf<<<HF_GRID, 512, HF_FLOATS * 4>>>(positions, weights, W1, b1,
                                          cng, cnb, bng, bnb, W2, b2, out);
}